// round 9
// baseline (speedup 1.0000x reference)
#include <cuda_runtime.h>
#include <cuda_bf16.h>
#include <cstdint>

#define N_NODES 50000
#define N_EDGES 800000
#define D 128
#define NW 128              // uint32 words per split row (hi/lo interleaved by column pair)
#define N_GRAPHS 128
#define OUT_DIM 16
#define SLOTS 64            // fixed adjacency slots per node (Poisson(16), P(>64)~1e-20)
#define STRA 136            // bf16 row stride for MMA tiles (272B: 16B-aligned, conflict-free)
#define IMG (128 * STRA)    // bf16 elems per 128x128 tile image (34816 B)
#define NT 391              // 128-row tiles covering N_NODES
#define GRID_GEMM 148       // persistent CTAs (all-resident)

// ---------------------------------------------------------------------------
// Scratch (no cudaMalloc allowed).  Features live in split-interleaved bf16:
// row = 128 uint32; word[2c] = bf16x2(hi of col 2c, hi of col 2c+1),
//                   word[2c+1] = bf16x2(lo pair).  value = hi + lo (~fp32).
// ---------------------------------------------------------------------------
__device__ uint32_t g_xs[N_NODES * NW];     // split x
__device__ uint32_t g_aggs[N_NODES * NW];   // split aggregation output
__device__ uint32_t g_h1[N_NODES * NW];     // split hidden ping
__device__ uint32_t g_h2[N_NODES * NW];     // split hidden pong
__device__ float g_sums[N_GRAPHS * D];
__device__ float g_cnt[N_GRAPHS];
__device__ int g_deg[N_NODES];
__device__ int g_adj[N_NODES * SLOTS];      // 12.8 MB
// Pre-split bf16 weights, transposed to [n][k], stride STRA.
// Per layer: [relHi][relLo][rootHi][rootLo], each IMG bf16.
__device__ __align__(16) __nv_bfloat16 g_Wsplit[3 * 4 * IMG];

// ---------------------------------------------------------------------------
// Helpers
// ---------------------------------------------------------------------------
__device__ __forceinline__ uint32_t smem_u32(const void* p) {
    uint32_t a;
    asm("{ .reg .u64 t; cvta.to.shared.u64 t, %1; cvt.u32.u64 %0, t; }"
        : "=r"(a) : "l"(p));
    return a;
}
__device__ __forceinline__ uint32_t pack_bf16(float lo, float hi) {
    uint32_t r;   // upper half <- hi, lower half <- lo
    asm("cvt.rn.bf16x2.f32 %0, %1, %2;" : "=r"(r) : "f"(hi), "f"(lo));
    return r;
}
__device__ __forceinline__ float up_lo(uint32_t w) {   // lower bf16 -> f32
    return __uint_as_float(w << 16);
}
__device__ __forceinline__ float up_hi(uint32_t w) {   // upper bf16 -> f32
    return __uint_as_float(w & 0xFFFF0000u);
}
// split pair (a = even col, b = odd col) -> {hi word, lo word}
__device__ __forceinline__ uint2 split2(float a, float b) {
    uint32_t hw = pack_bf16(a, b);
    float l0 = a - up_lo(hw);
    float l1 = b - up_hi(hw);
    uint32_t lw = pack_bf16(l0, l1);
    return make_uint2(hw, lw);
}
__device__ __forceinline__ void ldsm4(uint32_t* r, uint32_t addr) {
    asm volatile("ldmatrix.sync.aligned.m8n8.x4.shared.b16 {%0,%1,%2,%3}, [%4];"
                 : "=r"(r[0]), "=r"(r[1]), "=r"(r[2]), "=r"(r[3]) : "r"(addr));
}
__device__ __forceinline__ void mma16816(float* c, const uint32_t* a,
                                         uint32_t b0, uint32_t b1) {
    asm volatile(
        "mma.sync.aligned.m16n8k16.row.col.f32.bf16.bf16.f32 "
        "{%0,%1,%2,%3}, {%4,%5,%6,%7}, {%8,%9}, {%0,%1,%2,%3};"
        : "+f"(c[0]), "+f"(c[1]), "+f"(c[2]), "+f"(c[3])
        : "r"(a[0]), "r"(a[1]), "r"(a[2]), "r"(a[3]), "r"(b0), "r"(b1));
}

// ---------------------------------------------------------------------------
// Setup: zero deg/pool, convert x -> split-interleaved
// ---------------------------------------------------------------------------
__global__ void k_setup(const float* __restrict__ x) {
    int i = blockIdx.x * blockDim.x + threadIdx.x;
    if (i < N_NODES) g_deg[i] = 0;
    if (i < N_GRAPHS * D) g_sums[i] = 0.f;
    if (i < N_GRAPHS) g_cnt[i] = 0.f;
    if (i < N_NODES * 32) {
        int node = i >> 5;
        int t4 = i & 31;
        float4 v = *reinterpret_cast<const float4*>(x + (size_t)node * D + t4 * 4);
        uint2 p0 = split2(v.x, v.y);
        uint2 p1 = split2(v.z, v.w);
        *reinterpret_cast<uint4*>(g_xs + (size_t)node * NW + t4 * 4) =
            make_uint4(p0.x, p0.y, p1.x, p1.y);
    }
}

__global__ void k_fill(const int* __restrict__ ei) {
    int e = blockIdx.x * blockDim.x + threadIdx.x;
    if (e < N_EDGES) {
        int dst = ei[N_EDGES + e];
        int p = atomicAdd(&g_deg[dst], 1);
        if (p < SLOTS) g_adj[dst * SLOTS + p] = ei[e];
    }
}

// Split W (k-major [k][n]) into bf16 hi/lo, transposed to [n][k], stride STRA.
__global__ __launch_bounds__(256) void k_wprep(const float* __restrict__ Wrel,
                                               const float* __restrict__ Wroot) {
    int m = blockIdx.x;
    int layer = m >> 1;
    int isroot = m & 1;
    const float* W = (isroot ? Wroot : Wrel) + layer * D * D;
    __nv_bfloat16* hiP = g_Wsplit + (layer * 4 + isroot * 2) * IMG;
    __nv_bfloat16* loP = hiP + IMG;
    for (int i = threadIdx.x; i < D * D; i += 256) {
        int n = i & 127;
        int k = i >> 7;
        float w = W[k * D + n];
        __nv_bfloat16 h = __float2bfloat16(w);
        __nv_bfloat16 l = __float2bfloat16(w - __bfloat162float(h));
        hiP[n * STRA + k] = h;
        loP[n * STRA + k] = l;
    }
}

// ---------------------------------------------------------------------------
// Gather: aggs[n] = split( sum_{s in adj(n)} (hi+lo)(h[s]) ).  One warp/node.
// ---------------------------------------------------------------------------
__global__ __launch_bounds__(256) void k_gather(const uint32_t* __restrict__ h) {
    int n = (blockIdx.x * blockDim.x + threadIdx.x) >> 5;
    if (n >= N_NODES) return;
    int lane = threadIdx.x & 31;
    int deg = g_deg[n];
    if (deg > SLOTS) deg = SLOTS;
    const int* adj = g_adj + n * SLOTS;
    float a0 = 0.f, a1 = 0.f, a2 = 0.f, a3 = 0.f;
    int i = 0;
    for (; i + 4 <= deg; i += 4) {
#pragma unroll
        for (int j = 0; j < 4; j++) {
            int s = adj[i + j];
            uint4 u = *reinterpret_cast<const uint4*>(h + (size_t)s * NW + lane * 4);
            a0 += up_lo(u.x) + up_lo(u.y);
            a1 += up_hi(u.x) + up_hi(u.y);
            a2 += up_lo(u.z) + up_lo(u.w);
            a3 += up_hi(u.z) + up_hi(u.w);
        }
    }
    for (; i < deg; i++) {
        int s = adj[i];
        uint4 u = *reinterpret_cast<const uint4*>(h + (size_t)s * NW + lane * 4);
        a0 += up_lo(u.x) + up_lo(u.y);
        a1 += up_hi(u.x) + up_hi(u.y);
        a2 += up_lo(u.z) + up_lo(u.w);
        a3 += up_hi(u.z) + up_hi(u.w);
    }
    uint2 p0 = split2(a0, a1);
    uint2 p1 = split2(a2, a3);
    *reinterpret_cast<uint4*>(g_aggs + (size_t)n * NW + lane * 4) =
        make_uint4(p0.x, p0.y, p1.x, p1.y);
}

// ---------------------------------------------------------------------------
// Persistent HMMA GraphConv GEMM:
//   hout[tile] = split( relu( agg@Wrel + hin@Wroot + b ) )
// 148 CTAs x 256 thr; weights loaded once; loop over 391 tiles.
// SMEM: W 4*34816 | AHI 34816 | ALO 34816 | bias 512  = 209408 B
// ---------------------------------------------------------------------------
#define SMB_AHI  139264
#define SMB_ALO  174080
#define SMB_BIAS 208896
#define SM_TOTAL 209408

// Copy one 128-row split tile from global into AHI/ALO smem (stride STRA).
__device__ __forceinline__ void copyA(const uint32_t* __restrict__ src, int row0,
                                      char* smem) {
    uint32_t* hiP = reinterpret_cast<uint32_t*>(smem + SMB_AHI);
    uint32_t* loP = reinterpret_cast<uint32_t*>(smem + SMB_ALO);
#pragma unroll
    for (int it = 0; it < 16; it++) {
        int idx = it * 256 + threadIdx.x;
        int row = idx >> 5;
        int t4 = idx & 31;
        int grow = row0 + row;
        uint4 u = make_uint4(0u, 0u, 0u, 0u);
        if (grow < N_NODES)
            u = *reinterpret_cast<const uint4*>(src + (size_t)grow * NW + t4 * 4);
        int wo = row * 68 + t4 * 2;     // 68 words = STRA bf16 per row
        *reinterpret_cast<uint2*>(hiP + wo) = make_uint2(u.x, u.z);
        *reinterpret_cast<uint2*>(loP + wo) = make_uint2(u.y, u.w);
    }
}

// One K=128 pass: c += Ahi*(Whi+Wlo) + Alo*Whi
__device__ __forceinline__ void mma_pass(float c[2][8][4], uint32_t sbase,
                                         int wimg, int mrow0, int ncol0, int lane) {
    uint32_t aHiBase = sbase + SMB_AHI;
    uint32_t aLoBase = sbase + SMB_ALO;
    uint32_t wHiBase = sbase + (uint32_t)(wimg * 34816);
    uint32_t wLoBase = wHiBase + 34816;
    int arow = (lane & 7) + ((lane >> 3) & 1) * 8;
    int akc = ((lane >> 4) & 1) * 8;
    int bn = (lane & 7) + ((lane >> 4) & 1) * 8;
    int bkc = ((lane >> 3) & 1) * 8;

#pragma unroll
    for (int ks = 0; ks < 8; ks++) {
        int k0 = ks * 16;
        uint32_t aHi[2][4], aLo[2][4];
#pragma unroll
        for (int mt = 0; mt < 2; mt++) {
            uint32_t off = (uint32_t)((mrow0 + mt * 16 + arow) * (STRA * 2) +
                                      (k0 + akc) * 2);
            ldsm4(aHi[mt], aHiBase + off);
            ldsm4(aLo[mt], aLoBase + off);
        }
#pragma unroll
        for (int np = 0; np < 4; np++) {
            uint32_t woff = (uint32_t)((ncol0 + np * 16 + bn) * (STRA * 2) +
                                       (k0 + bkc) * 2);
            uint32_t b[4];
            ldsm4(b, wHiBase + woff);
#pragma unroll
            for (int mt = 0; mt < 2; mt++) {
                mma16816(c[mt][np * 2], aHi[mt], b[0], b[1]);
                mma16816(c[mt][np * 2 + 1], aHi[mt], b[2], b[3]);
                mma16816(c[mt][np * 2], aLo[mt], b[0], b[1]);
                mma16816(c[mt][np * 2 + 1], aLo[mt], b[2], b[3]);
            }
            ldsm4(b, wLoBase + woff);
#pragma unroll
            for (int mt = 0; mt < 2; mt++) {
                mma16816(c[mt][np * 2], aHi[mt], b[0], b[1]);
                mma16816(c[mt][np * 2 + 1], aHi[mt], b[2], b[3]);
            }
        }
    }
}

__global__ __launch_bounds__(256, 1)
void k_gemm_mma(const uint32_t* __restrict__ hin,
                const __nv_bfloat16* __restrict__ wlayer,  // 4 images
                const float* __restrict__ bias,
                uint32_t* __restrict__ hout) {
    extern __shared__ char smem[];
    int tid = threadIdx.x;
    int w = tid >> 5;
    int lane = tid & 31;
    int mrow0 = (w & 3) * 32;
    int ncol0 = (w >> 2) * 64;
    uint32_t sbase = smem_u32(smem);

    // Weights once per CTA (139264 B)
    {
        const float4* s4 = reinterpret_cast<const float4*>(wlayer);
        float4* d4 = reinterpret_cast<float4*>(smem);
#pragma unroll
        for (int i = 0; i < 34; i++) d4[i * 256 + tid] = s4[i * 256 + tid];
    }
    if (tid < 128) ((float*)(smem + SMB_BIAS))[tid] = bias[tid];
    __syncthreads();

    const float* sb = (const float*)(smem + SMB_BIAS);
    int g = lane >> 2;
    int t = lane & 3;

    for (int tile = blockIdx.x; tile < NT; tile += GRID_GEMM) {
        int row0 = tile * 128;

        copyA(g_aggs, row0, smem);
        __syncthreads();

        float c[2][8][4];
#pragma unroll
        for (int mt = 0; mt < 2; mt++)
#pragma unroll
            for (int nt = 0; nt < 8; nt++)
#pragma unroll
                for (int i = 0; i < 4; i++) c[mt][nt][i] = 0.f;

        mma_pass(c, sbase, 0, mrow0, ncol0, lane);   // agg @ Wrel
        __syncthreads();
        copyA(hin, row0, smem);
        __syncthreads();
        mma_pass(c, sbase, 2, mrow0, ncol0, lane);   // hin @ Wroot

        // Epilogue: bias + relu, write split-interleaved
#pragma unroll
        for (int mt = 0; mt < 2; mt++) {
#pragma unroll
            for (int nt = 0; nt < 8; nt++) {
                int col = ncol0 + nt * 8 + t * 2;
                float b0 = sb[col], b1 = sb[col + 1];
                int r0 = row0 + mrow0 + mt * 16 + g;
                if (r0 < N_NODES) {
                    uint2 p = split2(fmaxf(c[mt][nt][0] + b0, 0.f),
                                     fmaxf(c[mt][nt][1] + b1, 0.f));
                    *reinterpret_cast<uint2*>(hout + (size_t)r0 * NW + col) = p;
                }
                int r1 = r0 + 8;
                if (r1 < N_NODES) {
                    uint2 p = split2(fmaxf(c[mt][nt][2] + b0, 0.f),
                                     fmaxf(c[mt][nt][3] + b1, 0.f));
                    *reinterpret_cast<uint2*>(hout + (size_t)r1 * NW + col) = p;
                }
            }
        }
        __syncthreads();   // A buffers free for next tile
    }
}

// ---------------------------------------------------------------------------
// Pool (reads split) + head
// ---------------------------------------------------------------------------
#define NODES_PER_WARP 4
__global__ __launch_bounds__(256) void k_pool(const uint32_t* __restrict__ h,
                                              const int* __restrict__ batch) {
    int gwarp = (blockIdx.x * blockDim.x + threadIdx.x) >> 5;
    int lane = threadIdx.x & 31;
#pragma unroll
    for (int i = 0; i < NODES_PER_WARP; i++) {
        int n = gwarp * NODES_PER_WARP + i;
        if (n >= N_NODES) return;
        int g = batch[n];
        uint4 u = *reinterpret_cast<const uint4*>(h + (size_t)n * NW + lane * 4);
        float v0 = up_lo(u.x) + up_lo(u.y);
        float v1 = up_hi(u.x) + up_hi(u.y);
        float v2 = up_lo(u.z) + up_lo(u.w);
        float v3 = up_hi(u.z) + up_hi(u.w);
        float* dp = g_sums + g * D + lane * 4;
        asm volatile("red.global.add.v4.f32 [%0], {%1,%2,%3,%4};"
                     :: "l"(dp), "f"(v0), "f"(v1), "f"(v2), "f"(v3)
                     : "memory");
        if (lane == 0) atomicAdd(&g_cnt[g], 1.0f);
    }
}

__global__ __launch_bounds__(128) void k_head(const float* __restrict__ W1,
                                              const float* __restrict__ b1,
                                              const float* __restrict__ W2,
                                              const float* __restrict__ b2,
                                              float* __restrict__ out) {
    __shared__ float pooled[D];
    __shared__ float t[D];
    int g = blockIdx.x;
    int tid = threadIdx.x;
    float cnt = fmaxf(g_cnt[g], 1.0f);
    pooled[tid] = g_sums[g * D + tid] / cnt;
    __syncthreads();

    float acc = b1[tid];
#pragma unroll 8
    for (int k = 0; k < D; k++) acc += pooled[k] * W1[k * D + tid];
    t[tid] = acc;
    __syncthreads();

    if (tid < OUT_DIM) {
        float o = b2[tid];
#pragma unroll 8
        for (int k = 0; k < D; k++) o += t[k] * W2[k * OUT_DIM + tid];
        out[g * OUT_DIM + tid] = o;
    }
}

// ---------------------------------------------------------------------------
// Launch sequence (graph-capturable: kernel launches only)
// ---------------------------------------------------------------------------
extern "C" void kernel_launch(void* const* d_in, const int* in_sizes, int n_in,
                              void* d_out, int out_size) {
    const float* x = (const float*)d_in[0];
    const int* ei = (const int*)d_in[1];      // int32 (JAX x64 disabled)
    const int* batch = (const int*)d_in[2];   // int32
    const float* Wrel = (const float*)d_in[3];
    const float* brel = (const float*)d_in[4];
    const float* Wroot = (const float*)d_in[5];
    const float* W1 = (const float*)d_in[6];
    const float* b1 = (const float*)d_in[7];
    const float* W2 = (const float*)d_in[8];
    const float* b2 = (const float*)d_in[9];
    float* out = (float*)d_out;

    cudaFuncSetAttribute(k_gemm_mma, cudaFuncAttributeMaxDynamicSharedMemorySize,
                         SM_TOTAL);

    uint32_t *xs, *h1, *h2;
    __nv_bfloat16* wsp;
    cudaGetSymbolAddress((void**)&xs, g_xs);
    cudaGetSymbolAddress((void**)&h1, g_h1);
    cudaGetSymbolAddress((void**)&h2, g_h2);
    cudaGetSymbolAddress((void**)&wsp, g_Wsplit);

    const int setup_blocks = (N_NODES * 32 + 255) / 256;
    const int edge_blocks = (N_EDGES + 255) / 256;
    const int gather_blocks = (N_NODES + 7) / 8;
    const int pool_blocks = (N_NODES + 8 * NODES_PER_WARP - 1) / (8 * NODES_PER_WARP);

    // Setup
    k_setup<<<setup_blocks, 256>>>(x);
    k_wprep<<<6, 256>>>(Wrel, Wroot);
    k_fill<<<edge_blocks, 256>>>(ei);

    // Layer 0: xs -> h1
    k_gather<<<gather_blocks, 256>>>(xs);
    k_gemm_mma<<<GRID_GEMM, 256, SM_TOTAL>>>(xs, wsp + 0 * 4 * IMG, brel, h1);
    // Layer 1: h1 -> h2
    k_gather<<<gather_blocks, 256>>>(h1);
    k_gemm_mma<<<GRID_GEMM, 256, SM_TOTAL>>>(h1, wsp + 1 * 4 * IMG, brel + D, h2);
    // Layer 2: h2 -> h1
    k_gather<<<gather_blocks, 256>>>(h2);
    k_gemm_mma<<<GRID_GEMM, 256, SM_TOTAL>>>(h2, wsp + 2 * 4 * IMG, brel + 2 * D, h1);

    // Pool + head
    k_pool<<<pool_blocks, 256>>>(h1, batch);
    k_head<<<N_GRAPHS, 128>>>(W1, b1, W2, b2, out);
}

// round 10
// speedup vs baseline: 1.1218x; 1.1218x over previous
#include <cuda_runtime.h>
#include <cuda_fp16.h>
#include <cstdint>

#define N_NODES 50000
#define N_EDGES 800000
#define D 128
#define NW 128              // uint32 words per split row (fp16 hi/lo interleaved by col pair)
#define N_GRAPHS 128
#define OUT_DIM 16
#define SLOTS 64            // fixed adjacency slots per node (Poisson(16), P(>64)~1e-20)
#define STRA 136            // fp16 row stride for MMA tiles (272B: 16B-aligned, conflict-free)
#define IMG (128 * STRA)    // fp16 elems per 128x128 tile image (34816 B)
#define NT 391              // 128-row tiles covering N_NODES
#define GRID_GEMM 148       // persistent CTAs
#define GT 512              // GEMM threads (16 warps)

// ---------------------------------------------------------------------------
// Scratch (no cudaMalloc allowed).  Features: fp16 split-interleaved rows:
// word[2c] = f16x2(hi of cols 2c,2c+1), word[2c+1] = f16x2(lo pair).
// value = hi + lo  (~22-bit accurate vs fp32).
// ---------------------------------------------------------------------------
__device__ uint32_t g_xs[N_NODES * NW];
__device__ uint32_t g_aggs[N_NODES * NW];
__device__ uint32_t g_h1[N_NODES * NW];
__device__ uint32_t g_h2[N_NODES * NW];
__device__ float g_sums[N_GRAPHS * D];
__device__ float g_cnt[N_GRAPHS];
__device__ int g_deg[N_NODES];
__device__ int g_adj[N_NODES * SLOTS];
// Single fp16 weight images, transposed to [n][k], stride STRA.
// Per layer: [rel][root], each IMG halfs.
__device__ __align__(16) __half g_Wf16[3 * 2 * IMG];

// ---------------------------------------------------------------------------
// Helpers
// ---------------------------------------------------------------------------
__device__ __forceinline__ uint32_t smem_u32(const void* p) {
    uint32_t a;
    asm("{ .reg .u64 t; cvta.to.shared.u64 t, %1; cvt.u32.u64 %0, t; }"
        : "=r"(a) : "l"(p));
    return a;
}
// two packed fp16 -> floats; .x = lower half, .y = upper half
__device__ __forceinline__ float2 up2(uint32_t w) {
    float2 f;
    asm("{ .reg .f16 h0, h1; mov.b32 {h0, h1}, %2;\n\t"
        "  cvt.f32.f16 %0, h0; cvt.f32.f16 %1, h1; }"
        : "=f"(f.x), "=f"(f.y) : "r"(w));
    return f;
}
// pack (a -> lower, b -> upper); first asm source lands in upper half
__device__ __forceinline__ uint32_t packh2(float a, float b) {
    uint32_t r;
    asm("cvt.rn.f16x2.f32 %0, %1, %2;" : "=r"(r) : "f"(b), "f"(a));
    return r;
}
// split pair (a = even col, b = odd col) -> {hi word, lo word}
__device__ __forceinline__ uint2 split2h(float a, float b) {
    uint32_t hw = packh2(a, b);
    float2 h = up2(hw);
    uint32_t lw = packh2(a - h.x, b - h.y);
    return make_uint2(hw, lw);
}
__device__ __forceinline__ void ldsm4(uint32_t* r, uint32_t addr) {
    asm volatile("ldmatrix.sync.aligned.m8n8.x4.shared.b16 {%0,%1,%2,%3}, [%4];"
                 : "=r"(r[0]), "=r"(r[1]), "=r"(r[2]), "=r"(r[3]) : "r"(addr));
}
__device__ __forceinline__ void mma16816h(float* c, const uint32_t* a,
                                          uint32_t b0, uint32_t b1) {
    asm volatile(
        "mma.sync.aligned.m16n8k16.row.col.f32.f16.f16.f32 "
        "{%0,%1,%2,%3}, {%4,%5,%6,%7}, {%8,%9}, {%0,%1,%2,%3};"
        : "+f"(c[0]), "+f"(c[1]), "+f"(c[2]), "+f"(c[3])
        : "r"(a[0]), "r"(a[1]), "r"(a[2]), "r"(a[3]), "r"(b0), "r"(b1));
}

// ---------------------------------------------------------------------------
// Setup: zero deg/pool, convert x -> fp16 split
// ---------------------------------------------------------------------------
__global__ void k_setup(const float* __restrict__ x) {
    int i = blockIdx.x * blockDim.x + threadIdx.x;
    if (i < N_NODES) g_deg[i] = 0;
    if (i < N_GRAPHS * D) g_sums[i] = 0.f;
    if (i < N_GRAPHS) g_cnt[i] = 0.f;
    if (i < N_NODES * 32) {
        int node = i >> 5;
        int t4 = i & 31;
        float4 v = *reinterpret_cast<const float4*>(x + (size_t)node * D + t4 * 4);
        uint2 p0 = split2h(v.x, v.y);
        uint2 p1 = split2h(v.z, v.w);
        *reinterpret_cast<uint4*>(g_xs + (size_t)node * NW + t4 * 4) =
            make_uint4(p0.x, p0.y, p1.x, p1.y);
    }
}

__global__ void k_fill(const int* __restrict__ ei) {
    int e = blockIdx.x * blockDim.x + threadIdx.x;
    if (e < N_EDGES) {
        int dst = ei[N_EDGES + e];
        int p = atomicAdd(&g_deg[dst], 1);
        if (p < SLOTS) g_adj[dst * SLOTS + p] = ei[e];
    }
}

// W (k-major [k][n]) -> single fp16 image, transposed to [n][k], stride STRA.
__global__ __launch_bounds__(256) void k_wprep(const float* __restrict__ Wrel,
                                               const float* __restrict__ Wroot) {
    int m = blockIdx.x;                       // layer*2 + isroot
    int layer = m >> 1;
    int isroot = m & 1;
    const float* W = (isroot ? Wroot : Wrel) + layer * D * D;
    __half* dst = g_Wf16 + m * IMG;
    for (int i = threadIdx.x; i < D * D; i += 256) {
        int n = i & 127;
        int k = i >> 7;
        dst[n * STRA + k] = __float2half(W[k * D + n]);
    }
}

// ---------------------------------------------------------------------------
// Gather: aggs[n] = split( sum_{s in adj(n)} (hi+lo)(h[s]) ).  One warp/node.
// ---------------------------------------------------------------------------
__global__ __launch_bounds__(256) void k_gather(const uint32_t* __restrict__ h) {
    int n = (blockIdx.x * blockDim.x + threadIdx.x) >> 5;
    if (n >= N_NODES) return;
    int lane = threadIdx.x & 31;
    int deg = g_deg[n];
    if (deg > SLOTS) deg = SLOTS;
    const int* adj = g_adj + n * SLOTS;
    float a0 = 0.f, a1 = 0.f, a2 = 0.f, a3 = 0.f;
    int i = 0;
    for (; i + 4 <= deg; i += 4) {
#pragma unroll
        for (int j = 0; j < 4; j++) {
            int s = adj[i + j];
            uint4 u = *reinterpret_cast<const uint4*>(h + (size_t)s * NW + lane * 4);
            float2 h0 = up2(u.x), l0 = up2(u.y), h1 = up2(u.z), l1 = up2(u.w);
            a0 += h0.x + l0.x;
            a1 += h0.y + l0.y;
            a2 += h1.x + l1.x;
            a3 += h1.y + l1.y;
        }
    }
    for (; i < deg; i++) {
        int s = adj[i];
        uint4 u = *reinterpret_cast<const uint4*>(h + (size_t)s * NW + lane * 4);
        float2 h0 = up2(u.x), l0 = up2(u.y), h1 = up2(u.z), l1 = up2(u.w);
        a0 += h0.x + l0.x;
        a1 += h0.y + l0.y;
        a2 += h1.x + l1.x;
        a3 += h1.y + l1.y;
    }
    uint2 p0 = split2h(a0, a1);
    uint2 p1 = split2h(a2, a3);
    *reinterpret_cast<uint4*>(g_aggs + (size_t)n * NW + lane * 4) =
        make_uint4(p0.x, p0.y, p1.x, p1.y);
}

// ---------------------------------------------------------------------------
// Persistent HMMA GraphConv GEMM, fp16 2-product:
//   hout = split( relu( (AggHi+AggLo)@Wrel + (HHi+HLo)@Wroot + b ) )
// 148 CTAs x 512 thr (16 warps, warp tile 32m x 32n).
// SMEM: W 2*34816 | AHI 34816 | ALO 34816 | bias 512 = 139776 B
// ---------------------------------------------------------------------------
#define SMB_AHI  69632
#define SMB_ALO  104448
#define SMB_BIAS 139264
#define SM_TOTAL 139776

// Copy one 128-row split tile into AHI/ALO smem (stride STRA).
__device__ __forceinline__ void copyA(const uint32_t* __restrict__ src, int row0,
                                      char* smem) {
    uint32_t* hiP = reinterpret_cast<uint32_t*>(smem + SMB_AHI);
    uint32_t* loP = reinterpret_cast<uint32_t*>(smem + SMB_ALO);
#pragma unroll
    for (int it = 0; it < 8; it++) {
        int idx = it * GT + threadIdx.x;
        int row = idx >> 5;
        int t4 = idx & 31;
        int grow = row0 + row;
        uint4 u = make_uint4(0u, 0u, 0u, 0u);
        if (grow < N_NODES)
            u = *reinterpret_cast<const uint4*>(src + (size_t)grow * NW + t4 * 4);
        int wo = row * 68 + t4 * 2;     // 68 words = STRA halfs per row
        *reinterpret_cast<uint2*>(hiP + wo) = make_uint2(u.x, u.z);
        *reinterpret_cast<uint2*>(loP + wo) = make_uint2(u.y, u.w);
    }
}

// One K=128 pass: c += (Ahi + Alo) @ W[wimg]
__device__ __forceinline__ void mma_pass(float c[2][4][4], uint32_t sbase,
                                         int wimg, int mrow0, int ncol0, int lane) {
    uint32_t aHiBase = sbase + SMB_AHI;
    uint32_t aLoBase = sbase + SMB_ALO;
    uint32_t wBase = sbase + (uint32_t)(wimg * 34816);
    int arow = (lane & 7) + ((lane >> 3) & 1) * 8;
    int akc = ((lane >> 4) & 1) * 8;
    int bn = (lane & 7) + ((lane >> 4) & 1) * 8;
    int bkc = ((lane >> 3) & 1) * 8;

#pragma unroll
    for (int ks = 0; ks < 8; ks++) {
        int k0 = ks * 16;
        uint32_t aHi[2][4], aLo[2][4];
#pragma unroll
        for (int mt = 0; mt < 2; mt++) {
            uint32_t off = (uint32_t)((mrow0 + mt * 16 + arow) * (STRA * 2) +
                                      (k0 + akc) * 2);
            ldsm4(aHi[mt], aHiBase + off);
            ldsm4(aLo[mt], aLoBase + off);
        }
#pragma unroll
        for (int np = 0; np < 2; np++) {
            uint32_t woff = (uint32_t)((ncol0 + np * 16 + bn) * (STRA * 2) +
                                       (k0 + bkc) * 2);
            uint32_t b[4];
            ldsm4(b, wBase + woff);
#pragma unroll
            for (int mt = 0; mt < 2; mt++) {
                mma16816h(c[mt][np * 2], aHi[mt], b[0], b[1]);
                mma16816h(c[mt][np * 2 + 1], aHi[mt], b[2], b[3]);
                mma16816h(c[mt][np * 2], aLo[mt], b[0], b[1]);
                mma16816h(c[mt][np * 2 + 1], aLo[mt], b[2], b[3]);
            }
        }
    }
}

__global__ __launch_bounds__(GT, 1)
void k_gemm_mma(const uint32_t* __restrict__ hin,
                const __half* __restrict__ wlayer,   // [rel][root] images
                const float* __restrict__ bias,
                uint32_t* __restrict__ hout) {
    extern __shared__ char smem[];
    int tid = threadIdx.x;
    int w = tid >> 5;
    int lane = tid & 31;
    int mrow0 = (w & 3) * 32;        // 4 m-warps
    int ncol0 = (w >> 2) * 32;       // 4 n-warps
    uint32_t sbase = smem_u32(smem);

    // Weights once per CTA (69632 B)
    {
        const float4* s4 = reinterpret_cast<const float4*>(wlayer);
        float4* d4 = reinterpret_cast<float4*>(smem);
        for (int i = tid; i < 4352; i += GT) d4[i] = s4[i];
    }
    if (tid < 128) ((float*)(smem + SMB_BIAS))[tid] = bias[tid];
    __syncthreads();

    const float* sb = (const float*)(smem + SMB_BIAS);
    int g = lane >> 2;
    int t = lane & 3;

    for (int tile = blockIdx.x; tile < NT; tile += GRID_GEMM) {
        int row0 = tile * 128;

        copyA(g_aggs, row0, smem);
        __syncthreads();

        float c[2][4][4];
#pragma unroll
        for (int mt = 0; mt < 2; mt++)
#pragma unroll
            for (int nt = 0; nt < 4; nt++)
#pragma unroll
                for (int i = 0; i < 4; i++) c[mt][nt][i] = 0.f;

        mma_pass(c, sbase, 0, mrow0, ncol0, lane);   // agg @ Wrel
        __syncthreads();
        copyA(hin, row0, smem);
        __syncthreads();
        mma_pass(c, sbase, 1, mrow0, ncol0, lane);   // hin @ Wroot

        // Epilogue: bias + relu, write fp16 split
#pragma unroll
        for (int mt = 0; mt < 2; mt++) {
#pragma unroll
            for (int nt = 0; nt < 4; nt++) {
                int col = ncol0 + nt * 8 + t * 2;
                float b0 = sb[col], b1 = sb[col + 1];
                int r0 = row0 + mrow0 + mt * 16 + g;
                if (r0 < N_NODES) {
                    uint2 p = split2h(fmaxf(c[mt][nt][0] + b0, 0.f),
                                      fmaxf(c[mt][nt][1] + b1, 0.f));
                    *reinterpret_cast<uint2*>(hout + (size_t)r0 * NW + col) = p;
                }
                int r1 = r0 + 8;
                if (r1 < N_NODES) {
                    uint2 p = split2h(fmaxf(c[mt][nt][2] + b0, 0.f),
                                      fmaxf(c[mt][nt][3] + b1, 0.f));
                    *reinterpret_cast<uint2*>(hout + (size_t)r1 * NW + col) = p;
                }
            }
        }
        __syncthreads();
    }
}

// ---------------------------------------------------------------------------
// Pool (reads fp16 split) + head
// ---------------------------------------------------------------------------
#define NODES_PER_WARP 4
__global__ __launch_bounds__(256) void k_pool(const uint32_t* __restrict__ h,
                                              const int* __restrict__ batch) {
    int gwarp = (blockIdx.x * blockDim.x + threadIdx.x) >> 5;
    int lane = threadIdx.x & 31;
#pragma unroll
    for (int i = 0; i < NODES_PER_WARP; i++) {
        int n = gwarp * NODES_PER_WARP + i;
        if (n >= N_NODES) return;
        int g = batch[n];
        uint4 u = *reinterpret_cast<const uint4*>(h + (size_t)n * NW + lane * 4);
        float2 h0 = up2(u.x), l0 = up2(u.y), h1 = up2(u.z), l1 = up2(u.w);
        float v0 = h0.x + l0.x;
        float v1 = h0.y + l0.y;
        float v2 = h1.x + l1.x;
        float v3 = h1.y + l1.y;
        float* dp = g_sums + g * D + lane * 4;
        asm volatile("red.global.add.v4.f32 [%0], {%1,%2,%3,%4};"
                     :: "l"(dp), "f"(v0), "f"(v1), "f"(v2), "f"(v3)
                     : "memory");
        if (lane == 0) atomicAdd(&g_cnt[g], 1.0f);
    }
}

__global__ __launch_bounds__(128) void k_head(const float* __restrict__ W1,
                                              const float* __restrict__ b1,
                                              const float* __restrict__ W2,
                                              const float* __restrict__ b2,
                                              float* __restrict__ out) {
    __shared__ float pooled[D];
    __shared__ float t[D];
    int g = blockIdx.x;
    int tid = threadIdx.x;
    float cnt = fmaxf(g_cnt[g], 1.0f);
    pooled[tid] = g_sums[g * D + tid] / cnt;
    __syncthreads();

    float acc = b1[tid];
#pragma unroll 8
    for (int k = 0; k < D; k++) acc += pooled[k] * W1[k * D + tid];
    t[tid] = acc;
    __syncthreads();

    if (tid < OUT_DIM) {
        float o = b2[tid];
#pragma unroll 8
        for (int k = 0; k < D; k++) o += t[k] * W2[k * OUT_DIM + tid];
        out[g * OUT_DIM + tid] = o;
    }
}

// ---------------------------------------------------------------------------
// Launch sequence (graph-capturable: kernel launches only)
// ---------------------------------------------------------------------------
extern "C" void kernel_launch(void* const* d_in, const int* in_sizes, int n_in,
                              void* d_out, int out_size) {
    const float* x = (const float*)d_in[0];
    const int* ei = (const int*)d_in[1];      // int32 (JAX x64 disabled)
    const int* batch = (const int*)d_in[2];   // int32
    const float* Wrel = (const float*)d_in[3];
    const float* brel = (const float*)d_in[4];
    const float* Wroot = (const float*)d_in[5];
    const float* W1 = (const float*)d_in[6];
    const float* b1 = (const float*)d_in[7];
    const float* W2 = (const float*)d_in[8];
    const float* b2 = (const float*)d_in[9];
    float* out = (float*)d_out;

    cudaFuncSetAttribute(k_gemm_mma, cudaFuncAttributeMaxDynamicSharedMemorySize,
                         SM_TOTAL);

    uint32_t *xs, *h1, *h2;
    __half* wfp;
    cudaGetSymbolAddress((void**)&xs, g_xs);
    cudaGetSymbolAddress((void**)&h1, g_h1);
    cudaGetSymbolAddress((void**)&h2, g_h2);
    cudaGetSymbolAddress((void**)&wfp, g_Wf16);

    const int setup_blocks = (N_NODES * 32 + 255) / 256;
    const int edge_blocks = (N_EDGES + 255) / 256;
    const int gather_blocks = (N_NODES + 7) / 8;
    const int pool_blocks = (N_NODES + 8 * NODES_PER_WARP - 1) / (8 * NODES_PER_WARP);

    // Setup
    k_setup<<<setup_blocks, 256>>>(x);
    k_wprep<<<6, 256>>>(Wrel, Wroot);
    k_fill<<<edge_blocks, 256>>>(ei);

    // Layer 0: xs -> h1
    k_gather<<<gather_blocks, 256>>>(xs);
    k_gemm_mma<<<GRID_GEMM, GT, SM_TOTAL>>>(xs, wfp + 0 * 2 * IMG, brel, h1);
    // Layer 1: h1 -> h2
    k_gather<<<gather_blocks, 256>>>(h1);
    k_gemm_mma<<<GRID_GEMM, GT, SM_TOTAL>>>(h1, wfp + 1 * 2 * IMG, brel + D, h2);
    // Layer 2: h2 -> h1
    k_gather<<<gather_blocks, 256>>>(h2);
    k_gemm_mma<<<GRID_GEMM, GT, SM_TOTAL>>>(h2, wfp + 2 * 2 * IMG, brel + 2 * D, h1);

    // Pool + head
    k_pool<<<pool_blocks, 256>>>(h1, batch);
    k_head<<<N_GRAPHS, 128>>>(W1, b1, W2, b2, out);
}